// round 16
// baseline (speedup 1.0000x reference)
#include <cuda_runtime.h>
#include <math.h>

#define HEADS 4
#define DOT   64
#define DIN   40
#define SMAX  4096

#define PTPB  256          // prep threads
#define FOLD_BLOCKS 40     // one block per W_k row c (computes all 4 heads)
#define FTPB  320          // fused kernel threads = rows per chunk (10 warps)
#define FWARP (FTPB / 32)
#define TILE_F4 (FTPB * 10 + FTPB / 4)   // 3280 float4 = 52,480 B padded x tile

// Folded projection: V[c*4+h] = sum_d W_k[c, h*64+d] * W_q[h,d] / sqrt(64).
// Rows 40..167 of W_k (the agg part of `combined`) contribute a per-(segment,
// head) additive constant, which cancels in the segment softmax -> the entire
// psi-MLP / segment-mean / rho path is dead code.
__device__ float g_V[DIN * HEADS];
__device__ int   g_starts[SMAX + 1];     // starts[s] = lower_bound(seg, s)

// ---------------------------------------------------------------------------
// Kernel 1 (prep): blocks [0,40) fold W_k with W_q; blocks [40,...) detect
// segment boundaries with int4 loads (4 elements/thread).
// ---------------------------------------------------------------------------
__global__ __launch_bounds__(PTPB)
void k_prep(const float* __restrict__ Wk, const float* __restrict__ Wq,
            const int* __restrict__ seg, int N, int S) {
    if (blockIdx.x < FOLD_BLOCKS) {
        const int c = blockIdx.x;
        const int h = threadIdx.x >> 6;        // 0..3
        const int d = threadIdx.x & 63;        // 0..63
        float p = Wk[c * (HEADS * DOT) + h * DOT + d] * Wq[h * DOT + d];
#pragma unroll
        for (int o = 16; o > 0; o >>= 1) p += __shfl_xor_sync(0xffffffffu, p, o);
        __shared__ float ws[8];
        if ((threadIdx.x & 31) == 0) ws[threadIdx.x >> 5] = p;
        __syncthreads();
        if (threadIdx.x < HEADS)
            g_V[c * HEADS + threadIdx.x] = (ws[2 * threadIdx.x] + ws[2 * threadIdx.x + 1]) * 0.125f;

        // tail elements when N not a multiple of 4
        if (blockIdx.x == 0 && threadIdx.x == 0 && (N & 3)) {
            for (int i = (N >> 2) << 2; i < N; i++) {
                const int p0 = i ? seg[i - 1] : -1;
                const int c0 = seg[i];
                for (int s = p0 + 1; s <= c0; s++) g_starts[s] = i;
                if (i == N - 1)
                    for (int s = c0 + 1; s <= S; s++) g_starts[s] = N;
            }
        }
    } else {
        const int j  = (blockIdx.x - FOLD_BLOCKS) * PTPB + threadIdx.x;  // int4 index
        const int n4 = N >> 2;
        if (j >= n4) return;
        const int4 v  = reinterpret_cast<const int4*>(seg)[j];
        const int base = j << 2;
        int p = (base == 0) ? -1 : seg[base - 1];
        for (int s = p + 1; s <= v.x; s++) g_starts[s] = base;     p = v.x;
        for (int s = p + 1; s <= v.y; s++) g_starts[s] = base + 1; p = v.y;
        for (int s = p + 1; s <= v.z; s++) g_starts[s] = base + 2; p = v.z;
        for (int s = p + 1; s <= v.w; s++) g_starts[s] = base + 3; p = v.w;
        if (base + 3 == N - 1)
            for (int s = p + 1; s <= S; s++) g_starts[s] = N;
    }
}

// ---------------------------------------------------------------------------
// Kernel 2 (fused z + softmax): one block per segment (rows contiguous).
// Fast path (len <= 320, ~mu+5sigma): single chunk — coalesced float4 load of
// the segment's x rows into a padded smem tile, one row per thread, z = x@V,
// e = exp(z) kept in REGISTERS across the block-sum reduction, then scaled
// stores. No max subtraction (softmax shift-invariant; |z|<~1 with He-init
// scales so exp is exact to fp32 roundoff). No global scratch, no e staging.
// ---------------------------------------------------------------------------
__inline__ __device__ float warpSum(float v) {
#pragma unroll
    for (int o = 16; o > 0; o >>= 1) v += __shfl_xor_sync(0xffffffffu, v, o);
    return v;
}

__global__ __launch_bounds__(FTPB, 4)
void k_fused(const float4* __restrict__ x4, float* __restrict__ out, int N) {
    extern __shared__ float4 tile[];      // TILE_F4
    __shared__ float Vs[DIN * HEADS];
    __shared__ float red[FWARP][4];
    __shared__ float fin[4];

    const int s  = blockIdx.x;
    const int st = g_starts[s], en = g_starts[s + 1], len = en - st;
    if (len <= 0) return;

    const int tid = threadIdx.x;
    const int wid = tid >> 5, lane = tid & 31;
    for (int i = tid; i < DIN * HEADS; i += FTPB) Vs[i] = g_V[i];

    const long seglo = (long)st * 10;
    const long seghi = (long)en * 10;

    if (len <= FTPB) {
        // ---------------- fast path: one row per thread ----------------
#pragma unroll
        for (int q = 0; q < 10; q++) {
            const int  idx = q * FTPB + tid;
            const long f   = seglo + idx;
            float4 v = make_float4(0.f, 0.f, 0.f, 0.f);
            if (f < seghi) v = x4[f];
            tile[idx + idx / 40] = v;
        }
        __syncthreads();

        float e0 = 0.f, e1 = 0.f, e2 = 0.f, e3 = 0.f;
        if (tid < len) {
            const float4* tr = &tile[tid * 10 + (tid >> 2)];
            float a0 = 0.f, a1 = 0.f, a2 = 0.f, a3 = 0.f;
#pragma unroll
            for (int q = 0; q < 10; q++) {
                float4 v = tr[q];
                const float* Vp = &Vs[q * 16];
                a0 += v.x * Vp[0];  a1 += v.x * Vp[1];  a2 += v.x * Vp[2];  a3 += v.x * Vp[3];
                a0 += v.y * Vp[4];  a1 += v.y * Vp[5];  a2 += v.y * Vp[6];  a3 += v.y * Vp[7];
                a0 += v.z * Vp[8];  a1 += v.z * Vp[9];  a2 += v.z * Vp[10]; a3 += v.z * Vp[11];
                a0 += v.w * Vp[12]; a1 += v.w * Vp[13]; a2 += v.w * Vp[14]; a3 += v.w * Vp[15];
            }
            e0 = __expf(a0); e1 = __expf(a1); e2 = __expf(a2); e3 = __expf(a3);
        }

        float sm0 = warpSum(e0), sm1 = warpSum(e1), sm2 = warpSum(e2), sm3 = warpSum(e3);
        if (lane == 0) { red[wid][0] = sm0; red[wid][1] = sm1; red[wid][2] = sm2; red[wid][3] = sm3; }
        __syncthreads();
        if (tid == 0) {
            float r0 = 0.f, r1 = 0.f, r2 = 0.f, r3 = 0.f;
            for (int w = 0; w < FWARP; w++) {
                r0 += red[w][0]; r1 += red[w][1]; r2 += red[w][2]; r3 += red[w][3];
            }
            fin[0] = 1.f / r0; fin[1] = 1.f / r1; fin[2] = 1.f / r2; fin[3] = 1.f / r3;
        }
        __syncthreads();

        if (tid < len) {
            const int i = st + tid;
            out[0 * (size_t)N + i] = e0 * fin[0];
            out[1 * (size_t)N + i] = e1 * fin[1];
            out[2 * (size_t)N + i] = e2 * fin[2];
            out[3 * (size_t)N + i] = e3 * fin[3];
        }
        return;
    }

    // ------------- pathological fallback (len > 320): chunked -------------
    float sm0 = 0.f, sm1 = 0.f, sm2 = 0.f, sm3 = 0.f;
    for (int pass = 0; pass < 2; pass++) {
        float R0 = 0.f, R1 = 0.f, R2 = 0.f, R3 = 0.f;
        if (pass == 1) { R0 = fin[0]; R1 = fin[1]; R2 = fin[2]; R3 = fin[3]; }
        for (int c0 = 0; c0 < len; c0 += FTPB) {
            const long cbase = seglo + (long)c0 * 10;
#pragma unroll
            for (int q = 0; q < 10; q++) {
                const int  idx = q * FTPB + tid;
                const long f   = cbase + idx;
                float4 v = make_float4(0.f, 0.f, 0.f, 0.f);
                if (f < seghi) v = x4[f];
                tile[idx + idx / 40] = v;
            }
            __syncthreads();
            const int r = c0 + tid;
            if (r < len) {
                const float4* tr = &tile[tid * 10 + (tid >> 2)];
                float a0 = 0.f, a1 = 0.f, a2 = 0.f, a3 = 0.f;
#pragma unroll
                for (int q = 0; q < 10; q++) {
                    float4 v = tr[q];
                    const float* Vp = &Vs[q * 16];
                    a0 += v.x * Vp[0];  a1 += v.x * Vp[1];  a2 += v.x * Vp[2];  a3 += v.x * Vp[3];
                    a0 += v.y * Vp[4];  a1 += v.y * Vp[5];  a2 += v.y * Vp[6];  a3 += v.y * Vp[7];
                    a0 += v.z * Vp[8];  a1 += v.z * Vp[9];  a2 += v.z * Vp[10]; a3 += v.z * Vp[11];
                    a0 += v.w * Vp[12]; a1 += v.w * Vp[13]; a2 += v.w * Vp[14]; a3 += v.w * Vp[15];
                }
                if (pass == 0) {
                    sm0 += __expf(a0); sm1 += __expf(a1); sm2 += __expf(a2); sm3 += __expf(a3);
                } else {
                    const int i = st + r;
                    out[0 * (size_t)N + i] = __expf(a0) * R0;
                    out[1 * (size_t)N + i] = __expf(a1) * R1;
                    out[2 * (size_t)N + i] = __expf(a2) * R2;
                    out[3 * (size_t)N + i] = __expf(a3) * R3;
                }
            }
            __syncthreads();
        }
        if (pass == 0) {
            sm0 = warpSum(sm0); sm1 = warpSum(sm1); sm2 = warpSum(sm2); sm3 = warpSum(sm3);
            if (lane == 0) { red[wid][0] = sm0; red[wid][1] = sm1; red[wid][2] = sm2; red[wid][3] = sm3; }
            __syncthreads();
            if (tid == 0) {
                float r0 = 0.f, r1 = 0.f, r2 = 0.f, r3 = 0.f;
                for (int w = 0; w < FWARP; w++) {
                    r0 += red[w][0]; r1 += red[w][1]; r2 += red[w][2]; r3 += red[w][3];
                }
                fin[0] = 1.f / r0; fin[1] = 1.f / r1; fin[2] = 1.f / r2; fin[3] = 1.f / r3;
            }
            __syncthreads();
        }
    }
}

// ---------------------------------------------------------------------------
// Inputs (metadata order): 0=inputs[N,40] f32, 1=segment_ids[N] i32,
// 2=lengths[S] i32 (unused), 3..10 = W1,b1,W2,b2,W3,b3,Wr,br (cancel out),
// 11=W_k[168,256] f32, 12=W_q[4,64] f32.  Output: [HEADS, N, 1] f32.
// ---------------------------------------------------------------------------
extern "C" void kernel_launch(void* const* d_in, const int* in_sizes, int n_in,
                              void* d_out, int out_size) {
    const float* x   = (const float*)d_in[0];
    const int*   seg = (const int*)d_in[1];
    const float* Wk  = (const float*)d_in[11];
    const float* Wq  = (const float*)d_in[12];
    float* out = (float*)d_out;

    const int N = in_sizes[1];   // 500000
    const int S = in_sizes[2];   // 2048

    static bool attr_done = false;
    const int dyn_bytes = TILE_F4 * sizeof(float4);   // 52,480 B
    if (!attr_done) {
        cudaFuncSetAttribute(k_fused, cudaFuncAttributeMaxDynamicSharedMemorySize, dyn_bytes);
        attr_done = true;
    }

    const int bnd_blocks = ((N >> 2) + PTPB - 1) / PTPB;
    k_prep<<<FOLD_BLOCKS + bnd_blocks, PTPB>>>(Wk, Wq, seg, N, S);
    k_fused<<<S, FTPB, dyn_bytes>>>((const float4*)x, out, N);
}

// round 17
// speedup vs baseline: 1.0102x; 1.0102x over previous
#include <cuda_runtime.h>
#include <math.h>

#define HEADS 4
#define DOT   64
#define DIN   40
#define SMAX  4096

#define PTPB  256          // prep threads
#define FOLD_BLOCKS 40     // one block per W_k row c (computes all 4 heads)
#define FTPB  320          // fused kernel threads = rows per chunk (10 warps)
#define FWARP (FTPB / 32)
#define TILE_F4 (FTPB * 10 + FTPB / 4)   // 3280 float4 = 52,480 B padded x tile

// Folded projection: V[c*4+h] = sum_d W_k[c, h*64+d] * W_q[h,d] / sqrt(64).
// Rows 40..167 of W_k (the agg part of `combined`) contribute a per-(segment,
// head) additive constant, which cancels in the segment softmax -> the entire
// psi-MLP / segment-mean / rho path is dead code.
__device__ float g_V[DIN * HEADS];
__device__ int   g_starts[SMAX + 1];     // starts[s] = lower_bound(seg, s)

// ---------------------------------------------------------------------------
// Kernel 1 (prep): blocks [0,40) fold W_k with W_q; blocks [40,...) detect
// segment boundaries with int4 loads (4 elements/thread).
// ---------------------------------------------------------------------------
__global__ __launch_bounds__(PTPB)
void k_prep(const float* __restrict__ Wk, const float* __restrict__ Wq,
            const int* __restrict__ seg, int N, int S) {
    if (blockIdx.x < FOLD_BLOCKS) {
        const int c = blockIdx.x;
        const int h = threadIdx.x >> 6;        // 0..3
        const int d = threadIdx.x & 63;        // 0..63
        float p = Wk[c * (HEADS * DOT) + h * DOT + d] * Wq[h * DOT + d];
#pragma unroll
        for (int o = 16; o > 0; o >>= 1) p += __shfl_xor_sync(0xffffffffu, p, o);
        __shared__ float ws[8];
        if ((threadIdx.x & 31) == 0) ws[threadIdx.x >> 5] = p;
        __syncthreads();
        if (threadIdx.x < HEADS)
            g_V[c * HEADS + threadIdx.x] = (ws[2 * threadIdx.x] + ws[2 * threadIdx.x + 1]) * 0.125f;

        // tail elements when N not a multiple of 4
        if (blockIdx.x == 0 && threadIdx.x == 0 && (N & 3)) {
            for (int i = (N >> 2) << 2; i < N; i++) {
                const int p0 = i ? seg[i - 1] : -1;
                const int c0 = seg[i];
                for (int s = p0 + 1; s <= c0; s++) g_starts[s] = i;
                if (i == N - 1)
                    for (int s = c0 + 1; s <= S; s++) g_starts[s] = N;
            }
        }
    } else {
        const int j  = (blockIdx.x - FOLD_BLOCKS) * PTPB + threadIdx.x;  // int4 index
        const int n4 = N >> 2;
        if (j >= n4) return;
        const int4 v  = reinterpret_cast<const int4*>(seg)[j];
        const int base = j << 2;
        int p = (base == 0) ? -1 : seg[base - 1];
        for (int s = p + 1; s <= v.x; s++) g_starts[s] = base;     p = v.x;
        for (int s = p + 1; s <= v.y; s++) g_starts[s] = base + 1; p = v.y;
        for (int s = p + 1; s <= v.z; s++) g_starts[s] = base + 2; p = v.z;
        for (int s = p + 1; s <= v.w; s++) g_starts[s] = base + 3; p = v.w;
        if (base + 3 == N - 1)
            for (int s = p + 1; s <= S; s++) g_starts[s] = N;
    }
}

// ---------------------------------------------------------------------------
// Kernel 2 (fused z + softmax): one block per segment (rows contiguous).
// Fast path (len <= 320, ~mu+5sigma): single chunk — coalesced float4 load of
// the segment's x rows into a padded smem tile, one row per thread, z = x@V,
// e = exp(z) kept in REGISTERS across the block-sum reduction, then scaled
// stores. No max subtraction (softmax shift-invariant; |z|<~1 with He-init
// scales so exp is exact to fp32 roundoff). No global scratch, no e staging.
// ---------------------------------------------------------------------------
__inline__ __device__ float warpSum(float v) {
#pragma unroll
    for (int o = 16; o > 0; o >>= 1) v += __shfl_xor_sync(0xffffffffu, v, o);
    return v;
}

__global__ __launch_bounds__(FTPB, 4)
void k_fused(const float4* __restrict__ x4, float* __restrict__ out, int N) {
    extern __shared__ float4 tile[];      // TILE_F4
    __shared__ float Vs[DIN * HEADS];
    __shared__ float red[FWARP][4];
    __shared__ float fin[4];

    const int s  = blockIdx.x;
    const int st = g_starts[s], en = g_starts[s + 1], len = en - st;
    if (len <= 0) return;

    const int tid = threadIdx.x;
    const int wid = tid >> 5, lane = tid & 31;
    for (int i = tid; i < DIN * HEADS; i += FTPB) Vs[i] = g_V[i];

    const long seglo = (long)st * 10;
    const long seghi = (long)en * 10;

    if (len <= FTPB) {
        // ---------------- fast path: one row per thread ----------------
#pragma unroll
        for (int q = 0; q < 10; q++) {
            const int  idx = q * FTPB + tid;
            const long f   = seglo + idx;
            float4 v = make_float4(0.f, 0.f, 0.f, 0.f);
            if (f < seghi) v = x4[f];
            tile[idx + idx / 40] = v;
        }
        __syncthreads();

        float e0 = 0.f, e1 = 0.f, e2 = 0.f, e3 = 0.f;
        if (tid < len) {
            const float4* tr = &tile[tid * 10 + (tid >> 2)];
            float a0 = 0.f, a1 = 0.f, a2 = 0.f, a3 = 0.f;
#pragma unroll
            for (int q = 0; q < 10; q++) {
                float4 v = tr[q];
                const float* Vp = &Vs[q * 16];
                a0 += v.x * Vp[0];  a1 += v.x * Vp[1];  a2 += v.x * Vp[2];  a3 += v.x * Vp[3];
                a0 += v.y * Vp[4];  a1 += v.y * Vp[5];  a2 += v.y * Vp[6];  a3 += v.y * Vp[7];
                a0 += v.z * Vp[8];  a1 += v.z * Vp[9];  a2 += v.z * Vp[10]; a3 += v.z * Vp[11];
                a0 += v.w * Vp[12]; a1 += v.w * Vp[13]; a2 += v.w * Vp[14]; a3 += v.w * Vp[15];
            }
            e0 = __expf(a0); e1 = __expf(a1); e2 = __expf(a2); e3 = __expf(a3);
        }

        float sm0 = warpSum(e0), sm1 = warpSum(e1), sm2 = warpSum(e2), sm3 = warpSum(e3);
        if (lane == 0) { red[wid][0] = sm0; red[wid][1] = sm1; red[wid][2] = sm2; red[wid][3] = sm3; }
        __syncthreads();
        if (tid == 0) {
            float r0 = 0.f, r1 = 0.f, r2 = 0.f, r3 = 0.f;
            for (int w = 0; w < FWARP; w++) {
                r0 += red[w][0]; r1 += red[w][1]; r2 += red[w][2]; r3 += red[w][3];
            }
            fin[0] = 1.f / r0; fin[1] = 1.f / r1; fin[2] = 1.f / r2; fin[3] = 1.f / r3;
        }
        __syncthreads();

        if (tid < len) {
            const int i = st + tid;
            out[0 * (size_t)N + i] = e0 * fin[0];
            out[1 * (size_t)N + i] = e1 * fin[1];
            out[2 * (size_t)N + i] = e2 * fin[2];
            out[3 * (size_t)N + i] = e3 * fin[3];
        }
        return;
    }

    // ------------- pathological fallback (len > 320): chunked -------------
    float sm0 = 0.f, sm1 = 0.f, sm2 = 0.f, sm3 = 0.f;
    for (int pass = 0; pass < 2; pass++) {
        float R0 = 0.f, R1 = 0.f, R2 = 0.f, R3 = 0.f;
        if (pass == 1) { R0 = fin[0]; R1 = fin[1]; R2 = fin[2]; R3 = fin[3]; }
        for (int c0 = 0; c0 < len; c0 += FTPB) {
            const long cbase = seglo + (long)c0 * 10;
#pragma unroll
            for (int q = 0; q < 10; q++) {
                const int  idx = q * FTPB + tid;
                const long f   = cbase + idx;
                float4 v = make_float4(0.f, 0.f, 0.f, 0.f);
                if (f < seghi) v = x4[f];
                tile[idx + idx / 40] = v;
            }
            __syncthreads();
            const int r = c0 + tid;
            if (r < len) {
                const float4* tr = &tile[tid * 10 + (tid >> 2)];
                float a0 = 0.f, a1 = 0.f, a2 = 0.f, a3 = 0.f;
#pragma unroll
                for (int q = 0; q < 10; q++) {
                    float4 v = tr[q];
                    const float* Vp = &Vs[q * 16];
                    a0 += v.x * Vp[0];  a1 += v.x * Vp[1];  a2 += v.x * Vp[2];  a3 += v.x * Vp[3];
                    a0 += v.y * Vp[4];  a1 += v.y * Vp[5];  a2 += v.y * Vp[6];  a3 += v.y * Vp[7];
                    a0 += v.z * Vp[8];  a1 += v.z * Vp[9];  a2 += v.z * Vp[10]; a3 += v.z * Vp[11];
                    a0 += v.w * Vp[12]; a1 += v.w * Vp[13]; a2 += v.w * Vp[14]; a3 += v.w * Vp[15];
                }
                if (pass == 0) {
                    sm0 += __expf(a0); sm1 += __expf(a1); sm2 += __expf(a2); sm3 += __expf(a3);
                } else {
                    const int i = st + r;
                    out[0 * (size_t)N + i] = __expf(a0) * R0;
                    out[1 * (size_t)N + i] = __expf(a1) * R1;
                    out[2 * (size_t)N + i] = __expf(a2) * R2;
                    out[3 * (size_t)N + i] = __expf(a3) * R3;
                }
            }
            __syncthreads();
        }
        if (pass == 0) {
            sm0 = warpSum(sm0); sm1 = warpSum(sm1); sm2 = warpSum(sm2); sm3 = warpSum(sm3);
            if (lane == 0) { red[wid][0] = sm0; red[wid][1] = sm1; red[wid][2] = sm2; red[wid][3] = sm3; }
            __syncthreads();
            if (tid == 0) {
                float r0 = 0.f, r1 = 0.f, r2 = 0.f, r3 = 0.f;
                for (int w = 0; w < FWARP; w++) {
                    r0 += red[w][0]; r1 += red[w][1]; r2 += red[w][2]; r3 += red[w][3];
                }
                fin[0] = 1.f / r0; fin[1] = 1.f / r1; fin[2] = 1.f / r2; fin[3] = 1.f / r3;
            }
            __syncthreads();
        }
    }
}

// ---------------------------------------------------------------------------
// Inputs (metadata order): 0=inputs[N,40] f32, 1=segment_ids[N] i32,
// 2=lengths[S] i32 (unused), 3..10 = W1,b1,W2,b2,W3,b3,Wr,br (cancel out),
// 11=W_k[168,256] f32, 12=W_q[4,64] f32.  Output: [HEADS, N, 1] f32.
// ---------------------------------------------------------------------------
extern "C" void kernel_launch(void* const* d_in, const int* in_sizes, int n_in,
                              void* d_out, int out_size) {
    const float* x   = (const float*)d_in[0];
    const int*   seg = (const int*)d_in[1];
    const float* Wk  = (const float*)d_in[11];
    const float* Wq  = (const float*)d_in[12];
    float* out = (float*)d_out;

    const int N = in_sizes[1];   // 500000
    const int S = in_sizes[2];   // 2048

    static bool attr_done = false;
    const int dyn_bytes = TILE_F4 * sizeof(float4);   // 52,480 B
    if (!attr_done) {
        cudaFuncSetAttribute(k_fused, cudaFuncAttributeMaxDynamicSharedMemorySize, dyn_bytes);
        attr_done = true;
    }

    const int bnd_blocks = ((N >> 2) + PTPB - 1) / PTPB;
    k_prep<<<FOLD_BLOCKS + bnd_blocks, PTPB>>>(Wk, Wq, seg, N, S);
    k_fused<<<S, FTPB, dyn_bytes>>>((const float4*)x, out, N);
}